// round 2
// baseline (speedup 1.0000x reference)
#include <cuda_runtime.h>
#include <cstdint>
#include <math.h>

#define T_STEPS 512
#define BATCH   32
#define EMBED   512
#define HID     1024
#define G4      4096   // 4*HID

#define NB 128         // persistent CTAs (one per SM, <=148 so all resident)
#define NT 256
#define HS 1025        // padded shared row stride for h (odd -> conflict-free scalar loads)

#define OFF_HN ((size_t)BATCH * T_STEPS * HID)          // 16777216
#define OFF_CN (OFF_HN + (size_t)BATCH * HID)           // +32768

// ---- scratch (device globals: no allocation allowed) ----
__device__ float g_xproj[(size_t)T_STEPS * G4 * BATCH]; // 256MB, layout [t][j][b]
__device__ float g_h[2][BATCH * HID];                   // ping-pong h
__device__ unsigned g_count;                             // barrier state (returns to 0 each run)
__device__ volatile unsigned g_gen;

// ---------------------------------------------------------------------------
// Software grid barrier (all NB CTAs resident by construction).
// ---------------------------------------------------------------------------
__device__ __forceinline__ void grid_barrier() {
    __syncthreads();
    if (threadIdx.x == 0) {
        unsigned gen = g_gen;
        __threadfence();
        unsigned prev = atomicAdd(&g_count, 1u);
        if (prev == NB - 1) {
            g_count = 0;
            __threadfence();
            g_gen = gen + 1;
        } else {
            while (g_gen == gen) { __nanosleep(64); }
        }
        __threadfence();
    }
    __syncthreads();
}

// ---------------------------------------------------------------------------
// Kernel 1: x_proj[t][j][b] = sum_e emb[ids[b][t]][e] * Wih[j][e]
// Classic 128x128x8 fp32 SGEMM, 8x8 per thread, embedding gather fused on A.
// ---------------------------------------------------------------------------
__global__ void __launch_bounds__(256, 2) xproj_gemm(
    const int* __restrict__ ids,
    const float* __restrict__ emb,
    const float* __restrict__ Wih)
{
    __shared__ float As[8][132];   // [k][m], padded stride 132 (conflict-free stores)
    __shared__ float Bs[8][132];   // [k][n]

    const int m0  = blockIdx.y * 128;
    const int n0  = blockIdx.x * 128;
    const int tid = threadIdx.x;

    // load-role mapping: each thread owns one (row, half-of-k) float4 per tile
    const int mm = tid >> 1;       // 0..127
    const int qa = tid & 1;        // 0..1  (k-quad)
    const int gm = m0 + mm;
    const int tt = gm >> 5;        // row m = t*32 + b
    const int bb = gm & 31;
    const float* arow = emb + (size_t)ids[bb * T_STEPS + tt] * EMBED;
    const float* brow = Wih + (size_t)(n0 + mm) * EMBED;

    // compute-role mapping: 16x16 thread grid, 8x8 accumulators each
    const int tm = tid >> 4;
    const int tn = tid & 15;

    float acc[8][8];
#pragma unroll
    for (int i = 0; i < 8; i++)
#pragma unroll
        for (int j = 0; j < 8; j++) acc[i][j] = 0.f;

    for (int k0 = 0; k0 < EMBED; k0 += 8) {
        float4 av = *(const float4*)(arow + k0 + qa * 4);
        float4 bv = *(const float4*)(brow + k0 + qa * 4);
        __syncthreads();   // previous tile fully consumed
        As[qa * 4 + 0][mm] = av.x;
        As[qa * 4 + 1][mm] = av.y;
        As[qa * 4 + 2][mm] = av.z;
        As[qa * 4 + 3][mm] = av.w;
        Bs[qa * 4 + 0][mm] = bv.x;
        Bs[qa * 4 + 1][mm] = bv.y;
        Bs[qa * 4 + 2][mm] = bv.z;
        Bs[qa * 4 + 3][mm] = bv.w;
        __syncthreads();

#pragma unroll
        for (int kk = 0; kk < 8; kk++) {
            float4 a0 = *(const float4*)(&As[kk][tm * 8]);
            float4 a1 = *(const float4*)(&As[kk][tm * 8 + 4]);
            float4 b0 = *(const float4*)(&Bs[kk][tn * 8]);
            float4 b1 = *(const float4*)(&Bs[kk][tn * 8 + 4]);
            float a[8] = {a0.x, a0.y, a0.z, a0.w, a1.x, a1.y, a1.z, a1.w};
            float b[8] = {b0.x, b0.y, b0.z, b0.w, b1.x, b1.y, b1.z, b1.w};
#pragma unroll
            for (int i = 0; i < 8; i++)
#pragma unroll
                for (int j = 0; j < 8; j++) acc[i][j] += a[i] * b[j];
        }
    }

    // epilogue: scatter to [t][j][b]
#pragma unroll
    for (int i = 0; i < 8; i++) {
        const int gmi = m0 + tm * 8 + i;
        const int t = gmi >> 5;
        const int b = gmi & 31;
        float* base = g_xproj + (size_t)t * G4 * BATCH + b;
#pragma unroll
        for (int j = 0; j < 8; j++) {
            const int n = n0 + tn * 8 + j;
            base[(size_t)n * BATCH] = acc[i][j];
        }
    }
}

// ---------------------------------------------------------------------------
// Kernel 2: persistent LSTM recurrence.
// CTA b owns n-slice [n0, n0+8) of H for all 32 batches -> 32 gate rows.
//   compute phase: thread (jq 0..7, bq 0..31) -> 4 gate rows x 1 batch
//   finalize phase: thread (fi 0..7, fb 0..31) -> gate fusion + c/h update
// h staged to shared per step with a quad-rotation swizzle:
//   element (b, k=4q+c) stored at col 4q + ((c + (q>>3)) & 3), row stride HS=1025
//   -> conflict-free stores (lanes vary q) AND conflict-free loads (lanes vary b)
// ---------------------------------------------------------------------------
__global__ void __launch_bounds__(NT, 1) lstm_seq(
    const float* __restrict__ h0,
    const float* __restrict__ c0,
    const float* __restrict__ Whh,
    float* __restrict__ out)
{
    extern __shared__ float sm[];
    float* h_s     = sm;             // 32 * 1025 floats
    float* gates_s = sm + 32 * HS;   // 32 * 32 floats

    const int tid = threadIdx.x;
    const int n0  = blockIdx.x * 8;

    // init h ping-pong buffer 0 (each CTA writes its own n-slice for all b)
    {
        const int b = tid >> 3;
        const int i = tid & 7;
        g_h[0][b * HID + n0 + i] = h0[b * HID + n0 + i];
    }

    // compute-role constants
    const int jq = tid >> 5;   // 0..7
    const int bq = tid & 31;
    int jrow[4];
#pragma unroll
    for (int r = 0; r < 4; r++) {
        const int rr = jq * 4 + r;                 // 0..31 within CTA
        jrow[r] = (rr >> 3) * HID + n0 + (rr & 7); // gate*H + n
    }
    const float* Wp0 = Whh + (size_t)jrow[0] * HID;
    const float* Wp1 = Whh + (size_t)jrow[1] * HID;
    const float* Wp2 = Whh + (size_t)jrow[2] * HID;
    const float* Wp3 = Whh + (size_t)jrow[3] * HID;

    // finalize-role constants; c lives in a register for the whole sequence
    const int fi = tid >> 5;   // 0..7
    const int fb = tid & 31;
    const int cidx = fb * HID + n0 + fi;
    float c_reg = c0[cidx];
    float h_reg = 0.f;

    grid_barrier();   // h0 fully materialized in g_h[0]

    for (int t = 0; t < T_STEPS; t++) {
        const float* hread = g_h[t & 1];
        float* hwrite      = g_h[(t & 1) ^ 1];

        // ---- stage h -> shared (coalesced LDG.128, rotated conflict-free STS)
        for (int idx = tid; idx < (BATCH * HID / 4); idx += NT) {
            const int b = idx >> 8;          // 0..31
            const int q = idx & 255;         // k-quad 0..255
            float4 v = __ldcg((const float4*)(hread + b * HID + q * 4));
            const int rot = (q >> 3) & 3;
            float* d = h_s + b * HS + q * 4;
            d[(0 + rot) & 3] = v.x;
            d[(1 + rot) & 3] = v.y;
            d[(2 + rot) & 3] = v.z;
            d[(3 + rot) & 3] = v.w;
        }
        __syncthreads();

        // ---- gates GEMM slice: acc = xproj[t][j][bq] + W_hh[j,:] . h[bq,:]
        const float* xp = g_xproj + (size_t)t * G4 * BATCH + bq;
        float acc0 = xp[(size_t)jrow[0] * BATCH];
        float acc1 = xp[(size_t)jrow[1] * BATCH];
        float acc2 = xp[(size_t)jrow[2] * BATCH];
        float acc3 = xp[(size_t)jrow[3] * BATCH];
        const float* hb = h_s + bq * HS;

#pragma unroll 4
        for (int kb = 0; kb < HID / 32; kb++) {   // 32 blocks of 32 k
            const int rot = kb & 3;               // constant per unrolled copy
            const int kbase = kb * 32;
#pragma unroll
            for (int kc = 0; kc < 32; kc += 4) {
                const int k = kbase + kc;
                const float hv0 = hb[k + ((0 + rot) & 3)];
                const float hv1 = hb[k + ((1 + rot) & 3)];
                const float hv2 = hb[k + ((2 + rot) & 3)];
                const float hv3 = hb[k + ((3 + rot) & 3)];
                const float4 w0 = *(const float4*)(Wp0 + k);
                const float4 w1 = *(const float4*)(Wp1 + k);
                const float4 w2 = *(const float4*)(Wp2 + k);
                const float4 w3 = *(const float4*)(Wp3 + k);
                acc0 += w0.x * hv0; acc0 += w0.y * hv1; acc0 += w0.z * hv2; acc0 += w0.w * hv3;
                acc1 += w1.x * hv0; acc1 += w1.y * hv1; acc1 += w1.z * hv2; acc1 += w1.w * hv3;
                acc2 += w2.x * hv0; acc2 += w2.y * hv1; acc2 += w2.z * hv2; acc2 += w2.w * hv3;
                acc3 += w3.x * hv0; acc3 += w3.y * hv1; acc3 += w3.z * hv2; acc3 += w3.w * hv3;
            }
        }

        gates_s[(jq * 4 + 0) * 32 + bq] = acc0;
        gates_s[(jq * 4 + 1) * 32 + bq] = acc1;
        gates_s[(jq * 4 + 2) * 32 + bq] = acc2;
        gates_s[(jq * 4 + 3) * 32 + bq] = acc3;
        __syncthreads();

        // ---- gate fusion + state update
        const float gi_ = gates_s[( 0 + fi) * 32 + fb];
        const float gf_ = gates_s[( 8 + fi) * 32 + fb];
        const float gg_ = gates_s[(16 + fi) * 32 + fb];
        const float go_ = gates_s[(24 + fi) * 32 + fb];
        const float I = 1.f / (1.f + expf(-gi_));
        const float F = 1.f / (1.f + expf(-gf_));
        const float O = 1.f / (1.f + expf(-go_));
        const float G = tanhf(gg_);
        c_reg = F * c_reg + I * G;
        h_reg = O * tanhf(c_reg);

        hwrite[cidx] = h_reg;
        out[((size_t)fb * T_STEPS + t) * HID + n0 + fi] = h_reg;

        grid_barrier();   // h fully published before next step's staging
    }

    // final states
    out[OFF_HN + cidx] = h_reg;
    out[OFF_CN + cidx] = c_reg;
}

// ---------------------------------------------------------------------------
extern "C" void kernel_launch(void* const* d_in, const int* in_sizes, int n_in,
                              void* d_out, int out_size)
{
    (void)in_sizes; (void)n_in; (void)out_size;
    const int*   ids = (const int*)  d_in[0];
    const float* h0  = (const float*)d_in[1];
    const float* c0  = (const float*)d_in[2];
    const float* emb = (const float*)d_in[3];
    const float* Wih = (const float*)d_in[4];
    const float* Whh = (const float*)d_in[5];
    float* out = (float*)d_out;

    const int smem_bytes = (32 * HS + 32 * 32) * (int)sizeof(float); // 135,296 B
    cudaFuncSetAttribute(lstm_seq, cudaFuncAttributeMaxDynamicSharedMemorySize, smem_bytes);

    dim3 ggrid(G4 / 128, (BATCH * T_STEPS) / 128);  // (32, 128)
    xproj_gemm<<<ggrid, 256>>>(ids, emb, Wih);
    lstm_seq<<<NB, NT, smem_bytes>>>(h0, c0, Whh, out);
}

// round 3
// speedup vs baseline: 1.6017x; 1.6017x over previous
#include <cuda_runtime.h>
#include <cstdint>
#include <math.h>

#define T_STEPS 512
#define BATCH   32
#define EMBED   512
#define HID     1024
#define G4      4096

#define NB 128
#define NT 256
#define HP 257                 // padded h-chunk row stride (floats)

#define OFF_HN ((size_t)BATCH * T_STEPS * HID)
#define OFF_CN (OFF_HN + (size_t)BATCH * HID)

typedef unsigned long long u64;

__device__ float g_xproj[(size_t)T_STEPS * G4 * BATCH]; // [t][j][b]
__device__ float g_h[2][BATCH * HID];
__device__ unsigned g_count;
__device__ volatile unsigned g_gen;

__device__ __forceinline__ void ffma2(u64 &d, u64 a, u64 b) {
    asm("fma.rn.f32x2 %0, %1, %2, %0;" : "+l"(d) : "l"(a), "l"(b));
}
__device__ __forceinline__ u64 pk2(float x, float y) {
    u64 r; asm("mov.b64 %0, {%1, %2};" : "=l"(r) : "f"(x), "f"(y)); return r;
}
__device__ __forceinline__ float2 upk(u64 v) {
    float2 r; asm("mov.b64 {%0, %1}, %2;" : "=f"(r.x), "=f"(r.y) : "l"(v)); return r;
}

__device__ __forceinline__ void grid_barrier() {
    __syncthreads();
    if (threadIdx.x == 0) {
        unsigned gen = g_gen;
        __threadfence();
        unsigned prev = atomicAdd(&g_count, 1u);
        if (prev == NB - 1) {
            g_count = 0;
            __threadfence();
            g_gen = gen + 1;
        } else {
            while (g_gen == gen) { __nanosleep(64); }
        }
        __threadfence();
    }
    __syncthreads();
}

// ---------------------------------------------------------------------------
// Kernel 1: x_proj[t][j][b] = sum_e emb[ids[b][t]][e] * Wih[j][e]  (unchanged)
// ---------------------------------------------------------------------------
__global__ void __launch_bounds__(256, 2) xproj_gemm(
    const int* __restrict__ ids,
    const float* __restrict__ emb,
    const float* __restrict__ Wih)
{
    __shared__ float As[8][132];
    __shared__ float Bs[8][132];

    const int m0  = blockIdx.y * 128;
    const int n0  = blockIdx.x * 128;
    const int tid = threadIdx.x;

    const int mm = tid >> 1;
    const int qa = tid & 1;
    const int gm = m0 + mm;
    const int tt = gm >> 5;
    const int bb = gm & 31;
    const float* arow = emb + (size_t)ids[bb * T_STEPS + tt] * EMBED;
    const float* brow = Wih + (size_t)(n0 + mm) * EMBED;

    const int tm = tid >> 4;
    const int tn = tid & 15;

    float acc[8][8];
#pragma unroll
    for (int i = 0; i < 8; i++)
#pragma unroll
        for (int j = 0; j < 8; j++) acc[i][j] = 0.f;

    for (int k0 = 0; k0 < EMBED; k0 += 8) {
        float4 av = *(const float4*)(arow + k0 + qa * 4);
        float4 bv = *(const float4*)(brow + k0 + qa * 4);
        __syncthreads();
        As[qa * 4 + 0][mm] = av.x; As[qa * 4 + 1][mm] = av.y;
        As[qa * 4 + 2][mm] = av.z; As[qa * 4 + 3][mm] = av.w;
        Bs[qa * 4 + 0][mm] = bv.x; Bs[qa * 4 + 1][mm] = bv.y;
        Bs[qa * 4 + 2][mm] = bv.z; Bs[qa * 4 + 3][mm] = bv.w;
        __syncthreads();

#pragma unroll
        for (int kk = 0; kk < 8; kk++) {
            float4 a0 = *(const float4*)(&As[kk][tm * 8]);
            float4 a1 = *(const float4*)(&As[kk][tm * 8 + 4]);
            float4 b0 = *(const float4*)(&Bs[kk][tn * 8]);
            float4 b1 = *(const float4*)(&Bs[kk][tn * 8 + 4]);
            float a[8] = {a0.x, a0.y, a0.z, a0.w, a1.x, a1.y, a1.z, a1.w};
            float b[8] = {b0.x, b0.y, b0.z, b0.w, b1.x, b1.y, b1.z, b1.w};
#pragma unroll
            for (int i = 0; i < 8; i++)
#pragma unroll
                for (int j = 0; j < 8; j++) acc[i][j] += a[i] * b[j];
        }
    }

#pragma unroll
    for (int i = 0; i < 8; i++) {
        const int gmi = m0 + tm * 8 + i;
        const int t = gmi >> 5;
        const int b = gmi & 31;
        float* base = g_xproj + (size_t)t * G4 * BATCH + b;
#pragma unroll
        for (int j = 0; j < 8; j++) {
            const int n = n0 + tn * 8 + j;
            base[(size_t)n * BATCH] = acc[i][j];
        }
    }
}

// ---------------------------------------------------------------------------
// Kernel 2: persistent LSTM. W_hh slice (32 rows x 1024) lives in smem.
// h processed in 4 chunks of 256 k, double-buffered, stride HP=257
// (conflict-free scalar STS: bank = b+4*seg+j; conflict-free LDS: lane=b).
// Warp (rg 0..3, kh 0..1): 8 rows (gate rg) x half-chunk k, lanes = batches.
// k-paired f32x2 accumulators; 2-way partial reduce via smem; fused epilogue.
// ---------------------------------------------------------------------------
__global__ void __launch_bounds__(NT, 1) lstm_seq(
    const float* __restrict__ h0,
    const float* __restrict__ c0,
    const float* __restrict__ Whh,
    float* __restrict__ out)
{
    extern __shared__ float sm[];
    float* Ws   = sm;                       // 32*1024 = 32768 floats (128KB)
    float* hbuf = sm + 32768;               // 2 * 32*HP = 16448 floats
    float* part = sm + 32768 + 2 * 32 * HP; // 2*32*32 = 2048 floats

    const int tid = threadIdx.x;
    const int n0  = blockIdx.x * 8;

    // ---- load W_hh slice into smem (once)
    {
        const int rr = tid >> 3, seg = tid & 7;
        const int grow = (rr >> 3) * HID + n0 + (rr & 7);
        const float4* src = (const float4*)(Whh + (size_t)grow * HID) + seg * 32;
        float4* dst = (float4*)(Ws + rr * 1024) + seg * 32;
#pragma unroll 8
        for (int q = 0; q < 32; q++) dst[q] = src[q];
    }
    // ---- init h ping-pong buffer 0
    { const int b = tid >> 3, i = tid & 7; g_h[0][b * HID + n0 + i] = h0[b * HID + n0 + i]; }

    const int wid  = tid >> 5, lane = tid & 31;
    const int rg   = wid >> 1, kh = wid & 1;
    const int sb   = tid >> 3, ss = tid & 7;   // staging role
    const int fi   = tid >> 5, fb = tid & 31;  // finalize role
    const int cidx = fb * HID + n0 + fi;
    float c_reg = c0[cidx];
    float h_reg = 0.f;

    const float* wbase = Ws + (rg * 8) * 1024 + kh * 128;

    grid_barrier();

    for (int t = 0; t < T_STEPS; t++) {
        const float* hread = g_h[t & 1];
        float* hwrite      = g_h[(t & 1) ^ 1];

        // prefetch x_proj gate contributions for this thread's state element
        const float* xpt = g_xproj + (size_t)t * G4 * BATCH;
        const float xg0 = xpt[(size_t)(0 * HID + n0 + fi) * BATCH + fb];
        const float xg1 = xpt[(size_t)(1 * HID + n0 + fi) * BATCH + fb];
        const float xg2 = xpt[(size_t)(2 * HID + n0 + fi) * BATCH + fb];
        const float xg3 = xpt[(size_t)(3 * HID + n0 + fi) * BATCH + fb];

        u64 acc[8];
#pragma unroll
        for (int j = 0; j < 8; j++) acc[j] = 0ull;

        // preload chunk 0
        float4 sreg[8];
        {
            const float4* gsrc = (const float4*)(hread + sb * HID) + ss;
#pragma unroll
            for (int i = 0; i < 8; i++) sreg[i] = __ldcg(gsrc + 8 * i);
        }

        for (int c = 0; c < 4; c++) {
            float* buf = hbuf + (c & 1) * (32 * HP);
            __syncthreads();   // buffer free
            {
                float* db = buf + sb * HP;
#pragma unroll
                for (int i = 0; i < 8; i++) {
                    const int kk = (ss + 8 * i) * 4;
                    db[kk + 0] = sreg[i].x; db[kk + 1] = sreg[i].y;
                    db[kk + 2] = sreg[i].z; db[kk + 3] = sreg[i].w;
                }
            }
            if (c < 3) {
                const float4* gsrc = (const float4*)(hread + sb * HID) + (c + 1) * 64 + ss;
#pragma unroll
                for (int i = 0; i < 8; i++) sreg[i] = __ldcg(gsrc + 8 * i);
            }
            __syncthreads();   // buffer ready

            const float* hb = buf + lane * HP + kh * 128;
            const float* wb = wbase + c * 256;
#pragma unroll 8
            for (int kk = 0; kk < 128; kk += 4) {
                const float hv0 = hb[kk], hv1 = hb[kk + 1];
                const float hv2 = hb[kk + 2], hv3 = hb[kk + 3];
                const u64 p01 = pk2(hv0, hv1);
                const u64 p23 = pk2(hv2, hv3);
#pragma unroll
                for (int j = 0; j < 8; j++) {
                    const ulonglong2 w = *(const ulonglong2*)(wb + j * 1024 + kk);
                    ffma2(acc[j], p01, w.x);
                    ffma2(acc[j], p23, w.y);
                }
            }
        }

        // fold pairs and write partials: part[kh][row][b]
#pragma unroll
        for (int j = 0; j < 8; j++) {
            float2 v = upk(acc[j]);
            part[kh * 1024 + (rg * 8 + j) * 32 + lane] = v.x + v.y;
        }
        __syncthreads();

        // gate fusion + state update (thread owns (n0+fi, fb))
        const float gi_ = xg0 + part[(0 * 8 + fi) * 32 + fb] + part[1024 + (0 * 8 + fi) * 32 + fb];
        const float gf_ = xg1 + part[(1 * 8 + fi) * 32 + fb] + part[1024 + (1 * 8 + fi) * 32 + fb];
        const float gg_ = xg2 + part[(2 * 8 + fi) * 32 + fb] + part[1024 + (2 * 8 + fi) * 32 + fb];
        const float go_ = xg3 + part[(3 * 8 + fi) * 32 + fb] + part[1024 + (3 * 8 + fi) * 32 + fb];
        const float I = 1.f / (1.f + expf(-gi_));
        const float F = 1.f / (1.f + expf(-gf_));
        const float O = 1.f / (1.f + expf(-go_));
        const float G = tanhf(gg_);
        c_reg = F * c_reg + I * G;
        h_reg = O * tanhf(c_reg);

        hwrite[cidx] = h_reg;
        out[((size_t)fb * T_STEPS + t) * HID + n0 + fi] = h_reg;

        grid_barrier();
    }

    out[OFF_HN + cidx] = h_reg;
    out[OFF_CN + cidx] = c_reg;
}

// ---------------------------------------------------------------------------
extern "C" void kernel_launch(void* const* d_in, const int* in_sizes, int n_in,
                              void* d_out, int out_size)
{
    (void)in_sizes; (void)n_in; (void)out_size;
    const int*   ids = (const int*)  d_in[0];
    const float* h0  = (const float*)d_in[1];
    const float* c0  = (const float*)d_in[2];
    const float* emb = (const float*)d_in[3];
    const float* Wih = (const float*)d_in[4];
    const float* Whh = (const float*)d_in[5];
    float* out = (float*)d_out;

    const int smem_bytes = (32768 + 2 * 32 * HP + 2048) * (int)sizeof(float); // 205,056 B
    cudaFuncSetAttribute(lstm_seq, cudaFuncAttributeMaxDynamicSharedMemorySize, smem_bytes);

    dim3 ggrid(G4 / 128, (BATCH * T_STEPS) / 128);
    xproj_gemm<<<ggrid, 256>>>(ids, emb, Wih);
    lstm_seq<<<NB, NT, smem_bytes>>>(h0, c0, Whh, out);
}

// round 4
// speedup vs baseline: 1.6318x; 1.0188x over previous
#include <cuda_runtime.h>
#include <cstdint>
#include <math.h>

#define T_STEPS 512
#define BATCH   32
#define EMBED   512
#define HID     1024
#define G4      4096

#define NB 128
#define NT 512
#define HP 258          // padded h-chunk row stride (even -> LDS.64 pairs)

#define OFF_HN ((size_t)BATCH * T_STEPS * HID)
#define OFF_CN (OFF_HN + (size_t)BATCH * HID)

typedef unsigned long long u64;

__device__ float g_xproj[(size_t)T_STEPS * G4 * BATCH]; // [t][j][b]
__device__ float g_h[2][BATCH * HID];
__device__ unsigned g_count;
__device__ volatile unsigned g_gen;

__device__ __forceinline__ void ffma2(u64 &d, u64 a, u64 b) {
    asm("fma.rn.f32x2 %0, %1, %2, %0;" : "+l"(d) : "l"(a), "l"(b));
}
__device__ __forceinline__ u64 pk2(float x, float y) {
    u64 r; asm("mov.b64 %0, {%1, %2};" : "=l"(r) : "f"(x), "f"(y)); return r;
}
__device__ __forceinline__ float2 upk(u64 v) {
    float2 r; asm("mov.b64 {%0, %1}, %2;" : "=f"(r.x), "=f"(r.y) : "l"(v)); return r;
}

__device__ __forceinline__ void grid_barrier() {
    __syncthreads();
    if (threadIdx.x == 0) {
        unsigned gen = g_gen;
        __threadfence();
        unsigned prev = atomicAdd(&g_count, 1u);
        if (prev == NB - 1) {
            g_count = 0;
            __threadfence();
            g_gen = gen + 1;
        } else {
            while (g_gen == gen) { __nanosleep(32); }
        }
        __threadfence();
    }
    __syncthreads();
}

// ---------------------------------------------------------------------------
// Kernel 1: x_proj[t][j][b] = sum_e emb[ids[b][t]][e] * Wih[j][e]
// 128x128x8 SGEMM, packed f32x2 accumulators (8 x 4 pair-accs per thread).
// ---------------------------------------------------------------------------
__global__ void __launch_bounds__(256, 2) xproj_gemm(
    const int* __restrict__ ids,
    const float* __restrict__ emb,
    const float* __restrict__ Wih)
{
    __shared__ float As[8][132];
    __shared__ float Bs[8][132];

    const int m0  = blockIdx.y * 128;
    const int n0  = blockIdx.x * 128;
    const int tid = threadIdx.x;

    const int mm = tid >> 1;
    const int qa = tid & 1;
    const int gm = m0 + mm;
    const int tt = gm >> 5;
    const int bb = gm & 31;
    const float* arow = emb + (size_t)ids[bb * T_STEPS + tt] * EMBED;
    const float* brow = Wih + (size_t)(n0 + mm) * EMBED;

    const int tm = tid >> 4;
    const int tn = tid & 15;

    u64 accp[8][4];
#pragma unroll
    for (int i = 0; i < 8; i++)
#pragma unroll
        for (int j = 0; j < 4; j++) accp[i][j] = 0ull;

    for (int k0 = 0; k0 < EMBED; k0 += 8) {
        float4 av = *(const float4*)(arow + k0 + qa * 4);
        float4 bv = *(const float4*)(brow + k0 + qa * 4);
        __syncthreads();
        As[qa * 4 + 0][mm] = av.x; As[qa * 4 + 1][mm] = av.y;
        As[qa * 4 + 2][mm] = av.z; As[qa * 4 + 3][mm] = av.w;
        Bs[qa * 4 + 0][mm] = bv.x; Bs[qa * 4 + 1][mm] = bv.y;
        Bs[qa * 4 + 2][mm] = bv.z; Bs[qa * 4 + 3][mm] = bv.w;
        __syncthreads();

#pragma unroll
        for (int kk = 0; kk < 8; kk++) {
            float4 a0 = *(const float4*)(&As[kk][tm * 8]);
            float4 a1 = *(const float4*)(&As[kk][tm * 8 + 4]);
            const u64* bp = (const u64*)(&Bs[kk][tn * 8]);   // 32B aligned
            u64 b0 = bp[0], b1 = bp[1], b2 = bp[2], b3 = bp[3];
            u64 ad[8];
            ad[0] = pk2(a0.x, a0.x); ad[1] = pk2(a0.y, a0.y);
            ad[2] = pk2(a0.z, a0.z); ad[3] = pk2(a0.w, a0.w);
            ad[4] = pk2(a1.x, a1.x); ad[5] = pk2(a1.y, a1.y);
            ad[6] = pk2(a1.z, a1.z); ad[7] = pk2(a1.w, a1.w);
#pragma unroll
            for (int i = 0; i < 8; i++) {
                ffma2(accp[i][0], ad[i], b0);
                ffma2(accp[i][1], ad[i], b1);
                ffma2(accp[i][2], ad[i], b2);
                ffma2(accp[i][3], ad[i], b3);
            }
        }
    }

#pragma unroll
    for (int i = 0; i < 8; i++) {
        const int gmi = m0 + tm * 8 + i;
        const int t = gmi >> 5;
        const int b = gmi & 31;
        float* base = g_xproj + (size_t)t * G4 * BATCH + b;
#pragma unroll
        for (int jp = 0; jp < 4; jp++) {
            float2 v = upk(accp[i][jp]);
            const int n = n0 + tn * 8 + jp * 2;
            base[(size_t)n * BATCH]       = v.x;
            base[(size_t)(n + 1) * BATCH] = v.y;
        }
    }
}

// ---------------------------------------------------------------------------
// Kernel 2: persistent LSTM, 512 threads (16 warps).
// W_hh slice (32 rows x 1024) resident in smem. h in 4 chunks of 256 k,
// double-buffered, stride HP=258 (k-pairs loadable as LDS.64 -> f32x2 operand).
// Warp (rg 0..3, kp 0..3): 8 rows x 64-k quarter of each chunk, lanes = batches.
// 4-way k-partials reduced via smem; fused gate epilogue on tid<256.
// ---------------------------------------------------------------------------
__global__ void __launch_bounds__(NT, 1) lstm_seq(
    const float* __restrict__ h0,
    const float* __restrict__ c0,
    const float* __restrict__ Whh,
    float* __restrict__ out)
{
    extern __shared__ float sm[];
    float* Ws   = sm;                       // 32*1024 floats (128KB)
    float* hbuf = sm + 32768;               // 2 * 32*HP = 16512 floats
    float* part = sm + 32768 + 2 * 32 * HP; // 4*32*32 = 4096 floats

    const int tid = threadIdx.x;
    const int n0  = blockIdx.x * 8;

    // ---- load W_hh slice into smem (once)
    {
        const int rr = tid >> 4, seg = tid & 15;
        const int grow = (rr >> 3) * HID + n0 + (rr & 7);
        const float4* src = (const float4*)(Whh + (size_t)grow * HID);
        float4* dst = (float4*)(Ws + rr * 1024);
#pragma unroll 4
        for (int q = 0; q < 16; q++) dst[seg + 16 * q] = src[seg + 16 * q];
    }
    // ---- init h ping-pong buffer 0
    if (tid < 256) {
        const int b = tid >> 3, i = tid & 7;
        g_h[0][b * HID + n0 + i] = h0[b * HID + n0 + i];
    }

    const int wid  = tid >> 5, lane = tid & 31;
    const int rg   = wid >> 2, kp = wid & 3;
    const int sb   = tid >> 4, ss = tid & 15;  // staging role (4 float4 each)
    const int fi   = (tid >> 5) & 7, fb = tid & 31; // finalize role (tid<256)
    const int cidx = fb * HID + n0 + fi;
    float c_reg = (tid < 256) ? c0[cidx] : 0.f;
    float h_reg = 0.f;

    const float* wbase = Ws + (rg * 8) * 1024 + kp * 64;

    grid_barrier();

    for (int t = 0; t < T_STEPS; t++) {
        const float* hread = g_h[t & 1];
        float* hwrite      = g_h[(t & 1) ^ 1];

        // prefetch x_proj gate contributions
        float xg0 = 0.f, xg1 = 0.f, xg2 = 0.f, xg3 = 0.f;
        if (tid < 256) {
            const float* xpt = g_xproj + (size_t)t * G4 * BATCH + fb;
            xg0 = xpt[(size_t)(0 * HID + n0 + fi) * BATCH];
            xg1 = xpt[(size_t)(1 * HID + n0 + fi) * BATCH];
            xg2 = xpt[(size_t)(2 * HID + n0 + fi) * BATCH];
            xg3 = xpt[(size_t)(3 * HID + n0 + fi) * BATCH];
        }

        u64 acc[8];
#pragma unroll
        for (int j = 0; j < 8; j++) acc[j] = 0ull;

        // preload chunk 0 (L2; bypass L1 for cross-SM coherence)
        float4 sreg[4];
        {
            const float4* gsrc = (const float4*)(hread + sb * HID);
#pragma unroll
            for (int i = 0; i < 4; i++) sreg[i] = __ldcg(gsrc + ss + 16 * i);
        }

        for (int c = 0; c < 4; c++) {
            float* buf = hbuf + (c & 1) * (32 * HP);
            __syncthreads();   // buffer free
            {
                float* db = buf + sb * HP;
#pragma unroll
                for (int i = 0; i < 4; i++) {
                    const int kk = (ss + 16 * i) * 4;
                    *(float2*)(db + kk)     = make_float2(sreg[i].x, sreg[i].y);
                    *(float2*)(db + kk + 2) = make_float2(sreg[i].z, sreg[i].w);
                }
            }
            if (c < 3) {
                const float4* gsrc = (const float4*)(hread + sb * HID) + (c + 1) * 64;
#pragma unroll
                for (int i = 0; i < 4; i++) sreg[i] = __ldcg(gsrc + ss + 16 * i);
            }
            __syncthreads();   // buffer ready

            const float* hb = buf + lane * HP + kp * 64;
            const float* wb = wbase + c * 256;
#pragma unroll
            for (int kk = 0; kk < 64; kk += 4) {
                const u64 p01 = *(const u64*)(hb + kk);      // LDS.64 pair
                const u64 p23 = *(const u64*)(hb + kk + 2);
#pragma unroll
                for (int j = 0; j < 8; j++) {
                    const ulonglong2 w = *(const ulonglong2*)(wb + j * 1024 + kk);
                    ffma2(acc[j], p01, w.x);
                    ffma2(acc[j], p23, w.y);
                }
            }
        }

        // fold pairs, write partials: part[kp][row][b]
#pragma unroll
        for (int j = 0; j < 8; j++) {
            float2 v = upk(acc[j]);
            part[kp * 1024 + (rg * 8 + j) * 32 + lane] = v.x + v.y;
        }
        __syncthreads();

        // gate fusion + state update (thread owns (n0+fi, fb))
        if (tid < 256) {
            float g[4] = {xg0, xg1, xg2, xg3};
#pragma unroll
            for (int gg = 0; gg < 4; gg++) {
                const int row = gg * 8 + fi;
#pragma unroll
                for (int kq = 0; kq < 4; kq++) g[gg] += part[kq * 1024 + row * 32 + fb];
            }
            const float I = 1.f / (1.f + expf(-g[0]));
            const float F = 1.f / (1.f + expf(-g[1]));
            const float G = tanhf(g[2]);
            const float O = 1.f / (1.f + expf(-g[3]));
            c_reg = F * c_reg + I * G;
            h_reg = O * tanhf(c_reg);

            hwrite[cidx] = h_reg;
            out[((size_t)fb * T_STEPS + t) * HID + n0 + fi] = h_reg;
        }

        grid_barrier();
    }

    if (tid < 256) {
        out[OFF_HN + cidx] = h_reg;
        out[OFF_CN + cidx] = c_reg;
    }
}

// ---------------------------------------------------------------------------
extern "C" void kernel_launch(void* const* d_in, const int* in_sizes, int n_in,
                              void* d_out, int out_size)
{
    (void)in_sizes; (void)n_in; (void)out_size;
    const int*   ids = (const int*)  d_in[0];
    const float* h0  = (const float*)d_in[1];
    const float* c0  = (const float*)d_in[2];
    const float* emb = (const float*)d_in[3];
    const float* Wih = (const float*)d_in[4];
    const float* Whh = (const float*)d_in[5];
    float* out = (float*)d_out;

    const int smem_bytes = (32768 + 2 * 32 * HP + 4096) * (int)sizeof(float); // 213,504 B
    cudaFuncSetAttribute(lstm_seq, cudaFuncAttributeMaxDynamicSharedMemorySize, smem_bytes);

    dim3 ggrid(G4 / 128, (BATCH * T_STEPS) / 128);
    xproj_gemm<<<ggrid, 256>>>(ids, emb, Wih);
    lstm_seq<<<NB, NT, smem_bytes>>>(h0, c0, Whh, out);
}

// round 5
// speedup vs baseline: 1.7214x; 1.0550x over previous
#include <cuda_runtime.h>
#include <cstdint>
#include <math.h>

#define T_STEPS 512
#define BATCH   32
#define EMBED   512
#define HID     1024
#define G4      4096

#define NB 128
#define NT 512
#define HBS 257          // padded h-chunk row stride (odd -> conflict-free LDS.32)
#define HBUF_FLOATS (32 * HBS)   // 8224 per buffer

#define OFF_HN ((size_t)BATCH * T_STEPS * HID)
#define OFF_CN (OFF_HN + (size_t)BATCH * HID)

typedef unsigned long long u64;

__device__ float g_xproj[(size_t)T_STEPS * G4 * BATCH]; // [t][j][b]
__device__ float g_h[2][BATCH * HID];
__device__ unsigned g_count;
__device__ volatile unsigned g_gen;

__device__ __forceinline__ void ffma2(u64 &d, u64 a, u64 b) {
    asm("fma.rn.f32x2 %0, %1, %2, %0;" : "+l"(d) : "l"(a), "l"(b));
}
__device__ __forceinline__ u64 pk2(float x, float y) {
    u64 r; asm("mov.b64 %0, {%1, %2};" : "=l"(r) : "f"(x), "f"(y)); return r;
}
__device__ __forceinline__ float2 upk(u64 v) {
    float2 r; asm("mov.b64 {%0, %1}, %2;" : "=f"(r.x), "=f"(r.y) : "l"(v)); return r;
}

__device__ __forceinline__ void grid_barrier() {
    __syncthreads();
    if (threadIdx.x == 0) {
        unsigned gen = g_gen;
        __threadfence();
        unsigned prev = atomicAdd(&g_count, 1u);
        if (prev == NB - 1) {
            g_count = 0;
            __threadfence();
            g_gen = gen + 1;
        } else {
            while (g_gen == gen) { __nanosleep(32); }
        }
        __threadfence();
    }
    __syncthreads();
}

// ---------------------------------------------------------------------------
// Kernel 1: x_proj[t][j][b] = sum_e emb[ids[b][t]][e] * Wih[j][e]
// 128x128x8 SGEMM, packed f32x2 accumulators. (unchanged from R4)
// ---------------------------------------------------------------------------
__global__ void __launch_bounds__(256, 2) xproj_gemm(
    const int* __restrict__ ids,
    const float* __restrict__ emb,
    const float* __restrict__ Wih)
{
    __shared__ float As[8][132];
    __shared__ float Bs[8][132];

    const int m0  = blockIdx.y * 128;
    const int n0  = blockIdx.x * 128;
    const int tid = threadIdx.x;

    const int mm = tid >> 1;
    const int qa = tid & 1;
    const int gm = m0 + mm;
    const int tt = gm >> 5;
    const int bb = gm & 31;
    const float* arow = emb + (size_t)ids[bb * T_STEPS + tt] * EMBED;
    const float* brow = Wih + (size_t)(n0 + mm) * EMBED;

    const int tm = tid >> 4;
    const int tn = tid & 15;

    u64 accp[8][4];
#pragma unroll
    for (int i = 0; i < 8; i++)
#pragma unroll
        for (int j = 0; j < 4; j++) accp[i][j] = 0ull;

    for (int k0 = 0; k0 < EMBED; k0 += 8) {
        float4 av = *(const float4*)(arow + k0 + qa * 4);
        float4 bv = *(const float4*)(brow + k0 + qa * 4);
        __syncthreads();
        As[qa * 4 + 0][mm] = av.x; As[qa * 4 + 1][mm] = av.y;
        As[qa * 4 + 2][mm] = av.z; As[qa * 4 + 3][mm] = av.w;
        Bs[qa * 4 + 0][mm] = bv.x; Bs[qa * 4 + 1][mm] = bv.y;
        Bs[qa * 4 + 2][mm] = bv.z; Bs[qa * 4 + 3][mm] = bv.w;
        __syncthreads();

#pragma unroll
        for (int kk = 0; kk < 8; kk++) {
            float4 a0 = *(const float4*)(&As[kk][tm * 8]);
            float4 a1 = *(const float4*)(&As[kk][tm * 8 + 4]);
            const u64* bp = (const u64*)(&Bs[kk][tn * 8]);
            u64 b0 = bp[0], b1 = bp[1], b2 = bp[2], b3 = bp[3];
            u64 ad[8];
            ad[0] = pk2(a0.x, a0.x); ad[1] = pk2(a0.y, a0.y);
            ad[2] = pk2(a0.z, a0.z); ad[3] = pk2(a0.w, a0.w);
            ad[4] = pk2(a1.x, a1.x); ad[5] = pk2(a1.y, a1.y);
            ad[6] = pk2(a1.z, a1.z); ad[7] = pk2(a1.w, a1.w);
#pragma unroll
            for (int i = 0; i < 8; i++) {
                ffma2(accp[i][0], ad[i], b0);
                ffma2(accp[i][1], ad[i], b1);
                ffma2(accp[i][2], ad[i], b2);
                ffma2(accp[i][3], ad[i], b3);
            }
        }
    }

#pragma unroll
    for (int i = 0; i < 8; i++) {
        const int gmi = m0 + tm * 8 + i;
        const int t = gmi >> 5;
        const int b = gmi & 31;
        float* base = g_xproj + (size_t)t * G4 * BATCH + b;
#pragma unroll
        for (int jp = 0; jp < 4; jp++) {
            float2 v = upk(accp[i][jp]);
            const int n = n0 + tn * 8 + jp * 2;
            base[(size_t)n * BATCH]       = v.x;
            base[(size_t)(n + 1) * BATCH] = v.y;
        }
    }
}

// ---------------------------------------------------------------------------
// Kernel 2: persistent LSTM, 512 threads (16 warps).
// W_hh slice (32 rows x 1024) resident in smem (row-major).
// Warp = (rh 0..1, ks 0..7): rows rh*16..+15, k-slice ks*32..+31 of each
// 256-k chunk (4 chunks, double-buffered, stride 257 -> conflict-free LDS.32).
// Each h element read from smem exactly once. acc[16] f32x2 in registers.
// 8-way k-partials in smem (overlaid on h buffer 0), fused gate epilogue.
// ---------------------------------------------------------------------------
__global__ void __launch_bounds__(NT, 1) lstm_seq(
    const float* __restrict__ h0,
    const float* __restrict__ c0,
    const float* __restrict__ Whh,
    float* __restrict__ out)
{
    extern __shared__ float sm[];
    float* Ws   = sm;              // 32*1024 floats (128KB)
    float* hbuf = sm + 32768;      // 2 * 8224 floats
    float* part = hbuf;            // overlay on buffer 0 (needs 8192 <= 8224)

    const int tid = threadIdx.x;
    const int n0  = blockIdx.x * 8;

    // ---- load W_hh slice into smem (once); row r = gate(r>>3)*8... mapping:
    // Ws row index rr (0..31) <-> global row (rr>>3)*HID + n0 + (rr&7)
    {
        const int rr = tid >> 4, seg = tid & 15;
        const int grow = (rr >> 3) * HID + n0 + (rr & 7);
        const float4* src = (const float4*)(Whh + (size_t)grow * HID);
        float4* dst = (float4*)(Ws + rr * 1024);
#pragma unroll 4
        for (int q = 0; q < 16; q++) dst[seg + 16 * q] = src[seg + 16 * q];
    }
    // ---- init h ping-pong buffer 0
    if (tid < 256) {
        const int b = tid >> 3, i = tid & 7;
        g_h[0][b * HID + n0 + i] = h0[b * HID + n0 + i];
    }

    const int wid  = tid >> 5, lane = tid & 31;
    const int rh   = wid >> 3;        // 0..1 : rows rh*16..rh*16+15
    const int ks   = wid & 7;         // 0..7 : k-slice within chunk
    const int sb   = tid >> 4, ss = tid & 15;        // staging role
    const int fi   = (tid >> 5) & 7, fb = tid & 31;  // finalize role (tid<256)
    const int cidx = fb * HID + n0 + fi;
    float c_reg = (tid < 256) ? c0[cidx] : 0.f;
    float h_reg = 0.f;

    const float* wbase = Ws + (rh * 16) * 1024 + ks * 32;

    grid_barrier();

    for (int t = 0; t < T_STEPS; t++) {
        const float* hread = g_h[t & 1];
        float* hwrite      = g_h[(t & 1) ^ 1];

        // prefetch x_proj gate contributions (latency hidden under compute)
        float xg0 = 0.f, xg1 = 0.f, xg2 = 0.f, xg3 = 0.f;
        if (tid < 256) {
            const float* xpt = g_xproj + (size_t)t * G4 * BATCH + fb;
            xg0 = xpt[(size_t)(0 * HID + n0 + fi) * BATCH];
            xg1 = xpt[(size_t)(1 * HID + n0 + fi) * BATCH];
            xg2 = xpt[(size_t)(2 * HID + n0 + fi) * BATCH];
            xg3 = xpt[(size_t)(3 * HID + n0 + fi) * BATCH];
        }

        u64 acc[16];
#pragma unroll
        for (int r = 0; r < 16; r++) acc[r] = 0ull;

        // preload chunk 0 (L2; bypass L1 for cross-SM coherence)
        float4 sreg[4];
        {
            const float4* gsrc = (const float4*)(hread + sb * HID);
#pragma unroll
            for (int i = 0; i < 4; i++) sreg[i] = __ldcg(gsrc + ss + 16 * i);
        }

#pragma unroll 1
        for (int c = 0; c < 4; c++) {
            float* buf = hbuf + (c & 1) * HBUF_FLOATS;
            __syncthreads();   // buffer free
            {
                float* db = buf + sb * HBS;
#pragma unroll
                for (int i = 0; i < 4; i++) {
                    const int kk = (ss + 16 * i) * 4;
                    db[kk + 0] = sreg[i].x; db[kk + 1] = sreg[i].y;
                    db[kk + 2] = sreg[i].z; db[kk + 3] = sreg[i].w;
                }
            }
            if (c < 3) {
                const float4* gsrc = (const float4*)(hread + sb * HID) + (c + 1) * 64;
#pragma unroll
                for (int i = 0; i < 4; i++) sreg[i] = __ldcg(gsrc + ss + 16 * i);
            }
            __syncthreads();   // buffer ready

            const float* hb = buf + lane * HBS + ks * 32;  // conflict-free scalar
            const float* wk = wbase + c * 256;
#pragma unroll
            for (int kq = 0; kq < 8; kq++) {
                const float hv0 = hb[kq * 4 + 0];
                const float hv1 = hb[kq * 4 + 1];
                const float hv2 = hb[kq * 4 + 2];
                const float hv3 = hb[kq * 4 + 3];
                const u64 p01 = pk2(hv0, hv1);
                const u64 p23 = pk2(hv2, hv3);
#pragma unroll
                for (int r = 0; r < 16; r++) {
                    const ulonglong2 w = *(const ulonglong2*)(wk + r * 1024 + kq * 4);
                    ffma2(acc[r], p01, w.x);
                    ffma2(acc[r], p23, w.y);
                }
            }
        }

        // fold pairs, write partials: part[ks][row][b]  (overlaid on buffer 0;
        // safe: all warps are past chunk-2 compute, and buffer 0 is next
        // written only after the grid barrier)
#pragma unroll
        for (int r = 0; r < 16; r++) {
            float2 v = upk(acc[r]);
            part[ks * 1024 + (rh * 16 + r) * 32 + lane] = v.x + v.y;
        }
        __syncthreads();

        // gate fusion + state update (thread owns (n0+fi, fb))
        if (tid < 256) {
            float g[4] = {xg0, xg1, xg2, xg3};
#pragma unroll
            for (int gg = 0; gg < 4; gg++) {
                const int row = gg * 8 + fi;
#pragma unroll
                for (int kq = 0; kq < 8; kq++) g[gg] += part[kq * 1024 + row * 32 + fb];
            }
            const float I = 1.f / (1.f + expf(-g[0]));
            const float F = 1.f / (1.f + expf(-g[1]));
            const float G = tanhf(g[2]);
            const float O = 1.f / (1.f + expf(-g[3]));
            c_reg = F * c_reg + I * G;
            h_reg = O * tanhf(c_reg);

            hwrite[cidx] = h_reg;
            out[((size_t)fb * T_STEPS + t) * HID + n0 + fi] = h_reg;
        }

        grid_barrier();
    }

    if (tid < 256) {
        out[OFF_HN + cidx] = h_reg;
        out[OFF_CN + cidx] = c_reg;
    }
}

// ---------------------------------------------------------------------------
extern "C" void kernel_launch(void* const* d_in, const int* in_sizes, int n_in,
                              void* d_out, int out_size)
{
    (void)in_sizes; (void)n_in; (void)out_size;
    const int*   ids = (const int*)  d_in[0];
    const float* h0  = (const float*)d_in[1];
    const float* c0  = (const float*)d_in[2];
    const float* emb = (const float*)d_in[3];
    const float* Wih = (const float*)d_in[4];
    const float* Whh = (const float*)d_in[5];
    float* out = (float*)d_out;

    const int smem_bytes = (32768 + 2 * HBUF_FLOATS) * (int)sizeof(float); // 196,864 B
    cudaFuncSetAttribute(lstm_seq, cudaFuncAttributeMaxDynamicSharedMemorySize, smem_bytes);

    dim3 ggrid(G4 / 128, (BATCH * T_STEPS) / 128);
    xproj_gemm<<<ggrid, 256>>>(ids, emb, Wih);
    lstm_seq<<<NB, NT, smem_bytes>>>(h0, c0, Whh, out);
}